// round 14
// baseline (speedup 1.0000x reference)
#include <cuda_runtime.h>

#define BB 32
#define CC 512
#define HC 128
#define HW 4096
#define GROUP 8            /* 8 batches * 512 planes * 16KB = 67MB << 126MB L2 */
#define NGROUP (BB / GROUP)
#define GPLANES (GROUP * CC)
#define EPS_BN 0.001f

// scratch (no device allocations allowed anywhere)
__device__ float g_s[BB * CC];      // pooled means [B, C]
__device__ float g_es[BB * CC];     // e * scale2   [B, C]
__device__ float g_shift[CC];       // shift2       [C]

// ---------------------------------------------------------------------------
// R: per-plane mean for one group, 2 planes/block (8 front-batched __ldcg
// loads -> fills L2 for S). Triggers PDL completion at the end.
// ---------------------------------------------------------------------------
__global__ void __launch_bounds__(256) se_reduce_g(const float* __restrict__ x,
                                                   int base_batch) {
    const int plane0 = base_batch * CC + blockIdx.x * 2;
    const float4* xp = reinterpret_cast<const float4*>(x) +
                       (size_t)plane0 * (HW / 4) + threadIdx.x;

    float4 v[8];
#pragma unroll
    for (int i = 0; i < 8; i++) v[i] = __ldcg(xp + i * 256);

    float sA = 0.f, sB = 0.f;
#pragma unroll
    for (int i = 0; i < 4; i++) sA += (v[i].x + v[i].y) + (v[i].z + v[i].w);
#pragma unroll
    for (int i = 4; i < 8; i++) sB += (v[i].x + v[i].y) + (v[i].z + v[i].w);

#pragma unroll
    for (int o = 16; o > 0; o >>= 1) {
        sA += __shfl_down_sync(0xffffffffu, sA, o);
        sB += __shfl_down_sync(0xffffffffu, sB, o);
    }

    __shared__ float redA[8], redB[8];
    if ((threadIdx.x & 31) == 0) {
        redA[threadIdx.x >> 5] = sA;
        redB[threadIdx.x >> 5] = sB;
    }
    __syncthreads();
    if (threadIdx.x == 0) {
        float a = 0.f, b = 0.f;
#pragma unroll
        for (int i = 0; i < 8; i++) { a += redA[i]; b += redB[i]; }
        g_s[plane0]     = a * (1.0f / HW);
        g_s[plane0 + 1] = b * (1.0f / HW);
    }
    cudaTriggerProgrammaticLaunchCompletion();
}

// ---------------------------------------------------------------------------
// E: excitation MLP for one group (GROUP blocks). Syncs on R, triggers after
// publishing g_es / g_shift.
// ---------------------------------------------------------------------------
__global__ void __launch_bounds__(256) se_excite_g(
    int base_batch,
    const float* __restrict__ w1, const float* __restrict__ g1,
    const float* __restrict__ b1, const float* __restrict__ m1,
    const float* __restrict__ v1, const float* __restrict__ w2,
    const float* __restrict__ g2, const float* __restrict__ b2,
    const float* __restrict__ m2, const float* __restrict__ v2) {
    __shared__ float s_s[CC];
    __shared__ float s_h[HC];
    const int b = base_batch + blockIdx.x;
    const int wid = threadIdx.x >> 5, lane = threadIdx.x & 31;

    cudaGridDependencySynchronize();               // wait for this group's means

    for (int i = threadIdx.x; i < CC; i += 256) s_s[i] = g_s[b * CC + i];
    __syncthreads();

#pragma unroll 2
    for (int r = 0; r < 16; r++) {
        const int j = wid * 16 + r;
        const float* wr = w1 + j * CC;
        float acc = 0.f;
#pragma unroll
        for (int i = 0; i < CC / 32; i++)
            acc = fmaf(wr[lane + 32 * i], s_s[lane + 32 * i], acc);
#pragma unroll
        for (int o = 16; o > 0; o >>= 1)
            acc += __shfl_down_sync(0xffffffffu, acc, o);
        if (lane == 0) {
            float hv = (acc - m1[j]) * (g1[j] * rsqrtf(v1[j] + EPS_BN)) + b1[j];
            s_h[j] = fmaxf(hv, 0.f);
        }
    }
    __syncthreads();

#pragma unroll 2
    for (int r = 0; r < 64; r++) {
        const int c = wid * 64 + r;
        const float* wr = w2 + c * HC;
        float acc = 0.f;
#pragma unroll
        for (int i = 0; i < HC / 32; i++)
            acc = fmaf(wr[lane + 32 * i], s_h[lane + 32 * i], acc);
#pragma unroll
        for (int o = 16; o > 0; o >>= 1)
            acc += __shfl_down_sync(0xffffffffu, acc, o);
        if (lane == 0) {
            const float sc2 = g2[c] * rsqrtf(v2[c] + EPS_BN);
            g_es[b * CC + c] = acc * sc2;
            if (b == 0) g_shift[c] = fmaf(-m2[c], sc2, b2[c]);
        }
    }
    __syncthreads();                               // all writes issued
    cudaTriggerProgrammaticLaunchCompletion();
}

// ---------------------------------------------------------------------------
// S: y = x*es + shift for one group. Prefetches x (L2 hits — independent of
// E) before the dependency sync, then writes: pure DRAM write stream at the
// ~3.7 TB/s write ceiling.
// ---------------------------------------------------------------------------
__global__ void __launch_bounds__(256) se_scale_g(const float* __restrict__ x,
                                                  float* __restrict__ y,
                                                  int base_batch) {
    const int plane = base_batch * CC + blockIdx.x;
    const size_t base = (size_t)plane * (HW / 4);
    const float4* xp = reinterpret_cast<const float4*>(x) + base + threadIdx.x;
    float4*       yp = reinterpret_cast<float4*>(y) + base + threadIdx.x;

    float4 v[4];
#pragma unroll
    for (int i = 0; i < 4; i++) v[i] = __ldcg(xp + i * 256);   // prefetch (L2)

    cudaGridDependencySynchronize();               // g_es / g_shift ready

    const float es    = g_es[plane];
    const float shift = g_shift[plane & (CC - 1)];

#pragma unroll
    for (int i = 0; i < 4; i++) {
        float4 o;
        o.x = fmaf(v[i].x, es, shift);
        o.y = fmaf(v[i].y, es, shift);
        o.z = fmaf(v[i].z, es, shift);
        o.w = fmaf(v[i].w, es, shift);
        __stcs(yp + i * 256, o);
    }
}

// ---------------------------------------------------------------------------
extern "C" void kernel_launch(void* const* d_in, const int* in_sizes, int n_in,
                              void* d_out, int out_size) {
    const float* x  = (const float*)d_in[0];
    const float* w1 = (const float*)d_in[1];
    const float* g1 = (const float*)d_in[2];
    const float* b1 = (const float*)d_in[3];
    const float* m1 = (const float*)d_in[4];
    const float* v1 = (const float*)d_in[5];
    const float* w2 = (const float*)d_in[6];
    const float* g2 = (const float*)d_in[7];
    const float* b2 = (const float*)d_in[8];
    const float* m2 = (const float*)d_in[9];
    const float* v2 = (const float*)d_in[10];
    float* y = (float*)d_out;

    cudaLaunchAttribute attr[1];
    attr[0].id = cudaLaunchAttributeProgrammaticStreamSerialization;
    attr[0].val.programmaticStreamSerializationAllowed = 1;

    for (int g = 0; g < NGROUP; g++) {
        const int base = g * GROUP;

        // R_g: PDL for g>0 (no data dependency on S_{g-1}; starts on its drain)
        if (g == 0) {
            se_reduce_g<<<GPLANES / 2, 256>>>(x, base);
        } else {
            cudaLaunchConfig_t cfg = {};
            cfg.gridDim = dim3(GPLANES / 2); cfg.blockDim = dim3(256);
            cfg.stream = 0; cfg.attrs = attr; cfg.numAttrs = 1;
            if (cudaLaunchKernelEx(&cfg, se_reduce_g, x, base) != cudaSuccess) {
                (void)cudaGetLastError();
                se_reduce_g<<<GPLANES / 2, 256>>>(x, base);
            }
        }

        // E_g
        {
            cudaLaunchConfig_t cfg = {};
            cfg.gridDim = dim3(GROUP); cfg.blockDim = dim3(256);
            cfg.stream = 0; cfg.attrs = attr; cfg.numAttrs = 1;
            if (cudaLaunchKernelEx(&cfg, se_excite_g, base,
                                   w1, g1, b1, m1, v1,
                                   w2, g2, b2, m2, v2) != cudaSuccess) {
                (void)cudaGetLastError();
                se_excite_g<<<GROUP, 256>>>(base, w1, g1, b1, m1, v1,
                                            w2, g2, b2, m2, v2);
            }
        }

        // S_g
        {
            cudaLaunchConfig_t cfg = {};
            cfg.gridDim = dim3(GPLANES); cfg.blockDim = dim3(256);
            cfg.stream = 0; cfg.attrs = attr; cfg.numAttrs = 1;
            if (cudaLaunchKernelEx(&cfg, se_scale_g, x, y, base) != cudaSuccess) {
                (void)cudaGetLastError();
                se_scale_g<<<GPLANES, 256>>>(x, y, base);
            }
        }
    }
}

// round 15
// speedup vs baseline: 1.7855x; 1.7855x over previous
#include <cuda_runtime.h>

#define BB 32
#define CC 512
#define HC 128
#define HW 4096
#define NPLANE (BB * CC)
#define CONS 512                     /* consumer blocks == planes per batch */
#define EPS_BN 0.001f

// scratch (no device allocations allowed anywhere); zero-init at load
__device__ float g_s[BB * CC];       // pooled means [B, C]
__device__ float g_es[BB * CC];      // e * scale2   [B, C]
__device__ float g_shift[CC];        // shift2       [C]
__device__ unsigned g_cnt[BB];       // per-batch reduce counters (self-reset)
__device__ int g_flag[BB];           // batch-ready flags (reset by consumer)
__device__ unsigned g_done;          // consumer completion counter (self-reset)

// ---------------------------------------------------------------------------
// PRODUCER: full-grid reduce (one block per plane, transient — never waits).
// The block that completes a batch computes that batch's excitation MLP
// (warp-cooperative, coalesced) and raises flag[batch].
// ---------------------------------------------------------------------------
__global__ void __launch_bounds__(256) se_produce(
    const float* __restrict__ x,
    const float* __restrict__ w1, const float* __restrict__ g1,
    const float* __restrict__ b1, const float* __restrict__ m1,
    const float* __restrict__ v1, const float* __restrict__ w2,
    const float* __restrict__ g2, const float* __restrict__ b2,
    const float* __restrict__ m2, const float* __restrict__ v2) {

    const int plane = blockIdx.x;
    const int batch = plane >> 9;
    const int tid = threadIdx.x, wid = tid >> 5, lane = tid & 31;

    const float4* xp = reinterpret_cast<const float4*>(x) +
                       (size_t)plane * (HW / 4) + tid;
    float sum = 0.f;
#pragma unroll
    for (int i = 0; i < 4; i++) {
        float4 v = __ldcg(xp + i * 256);           // fill L2 for the consumer
        sum += (v.x + v.y) + (v.z + v.w);
    }
#pragma unroll
    for (int o = 16; o > 0; o >>= 1)
        sum += __shfl_down_sync(0xffffffffu, sum, o);

    __shared__ float red[8];
    __shared__ int s_last;
    if (lane == 0) red[wid] = sum;
    __syncthreads();
    if (tid == 0) {
        float s = 0.f;
#pragma unroll
        for (int i = 0; i < 8; i++) s += red[i];
        g_s[plane] = s * (1.0f / HW);
        __threadfence();                            // release mean
        unsigned old = atomicAdd(&g_cnt[batch], 1u);
        s_last = (old == CC - 1);
    }
    __syncthreads();
    if (!s_last) return;

    // ---- tail block: excitation MLP for this batch ----
    __threadfence();                                // acquire peers' means
    __shared__ float s_s[CC];
    __shared__ float s_h[HC];
    for (int i = tid; i < CC; i += 256) s_s[i] = __ldcg(&g_s[batch * CC + i]);
    __syncthreads();

#pragma unroll 2
    for (int r = 0; r < 16; r++) {
        const int j = wid * 16 + r;
        const float* wr = w1 + j * CC;
        float acc = 0.f;
#pragma unroll
        for (int i = 0; i < CC / 32; i++)
            acc = fmaf(wr[lane + 32 * i], s_s[lane + 32 * i], acc);
#pragma unroll
        for (int o = 16; o > 0; o >>= 1)
            acc += __shfl_down_sync(0xffffffffu, acc, o);
        if (lane == 0) {
            float hv = (acc - m1[j]) * (g1[j] * rsqrtf(v1[j] + EPS_BN)) + b1[j];
            s_h[j] = fmaxf(hv, 0.f);
        }
    }
    __syncthreads();

#pragma unroll 2
    for (int r = 0; r < 64; r++) {
        const int c = wid * 64 + r;
        const float* wr = w2 + c * HC;
        float acc = 0.f;
#pragma unroll
        for (int i = 0; i < HC / 32; i++)
            acc = fmaf(wr[lane + 32 * i], s_h[lane + 32 * i], acc);
#pragma unroll
        for (int o = 16; o > 0; o >>= 1)
            acc += __shfl_down_sync(0xffffffffu, acc, o);
        if (lane == 0) {
            const float sc2 = g2[c] * rsqrtf(v2[c] + EPS_BN);
            g_es[batch * CC + c] = acc * sc2;
            g_shift[c] = fmaf(-m2[c], sc2, b2[c]);  // every batch: benign dup
        }
    }
    __syncthreads();
    if (tid == 0) {
        g_cnt[batch] = 0;                           // self-reset for replay
        __threadfence();                            // release es/shift
        atomicExch(&g_flag[batch], 1);
    }
}

// ---------------------------------------------------------------------------
// CONSUMER: persistent 512-block kernel on a parallel graph branch.
// Block bid handles plane k*512+bid for each batch k: wait flag[k] (producer
// is always making progress -> no deadlock), read x (L2-hot), write y.
// ---------------------------------------------------------------------------
__global__ void __launch_bounds__(256) se_consume(const float* __restrict__ x,
                                                  float* __restrict__ y) {
    const int tid = threadIdx.x;

    for (int k = 0; k < BB; k++) {
        const int plane = k * CC + blockIdx.x;

        if (tid == 0) {
            while (*(volatile int*)&g_flag[k] == 0) __nanosleep(128);
            __threadfence();                        // acquire es/shift
        }
        __syncthreads();

        const float es    = __ldcg(&g_es[plane]);
        const float shift = __ldcg(&g_shift[plane & (CC - 1)]);

        const size_t base = (size_t)plane * (HW / 4);
        const float4* xp = reinterpret_cast<const float4*>(x) + base + tid;
        float4*       yp = reinterpret_cast<float4*>(y) + base + tid;

        float4 v[4];
#pragma unroll
        for (int i = 0; i < 4; i++) v[i] = __ldcg(xp + i * 256);
#pragma unroll
        for (int i = 0; i < 4; i++) {
            float4 o;
            o.x = fmaf(v[i].x, es, shift);
            o.y = fmaf(v[i].y, es, shift);
            o.z = fmaf(v[i].z, es, shift);
            o.w = fmaf(v[i].w, es, shift);
            __stcs(yp + i * 256, o);
        }
    }

    // reset flags for the next graph replay (last consumer block cleans up)
    __syncthreads();
    if (tid == 0) {
        unsigned d = atomicAdd(&g_done, 1u);
        if (d == CONS - 1) {
#pragma unroll
            for (int b = 0; b < BB; b++) g_flag[b] = 0;
            g_done = 0;
        }
    }
}

// ---------------------------------------------------------------------------
// Fork two parallel graph branches: producer on the caller's stream,
// consumer on a side stream (no cross-dependency) -> they run concurrently.
// ---------------------------------------------------------------------------
extern "C" void kernel_launch(void* const* d_in, const int* in_sizes, int n_in,
                              void* d_out, int out_size) {
    const float* x  = (const float*)d_in[0];
    const float* w1 = (const float*)d_in[1];
    const float* g1 = (const float*)d_in[2];
    const float* b1 = (const float*)d_in[3];
    const float* m1 = (const float*)d_in[4];
    const float* v1 = (const float*)d_in[5];
    const float* w2 = (const float*)d_in[6];
    const float* g2 = (const float*)d_in[7];
    const float* b2 = (const float*)d_in[8];
    const float* m2 = (const float*)d_in[9];
    const float* v2 = (const float*)d_in[10];
    float* y = (float*)d_out;

    static cudaStream_t side = nullptr;
    static cudaEvent_t ev_fork, ev_join;
    if (side == nullptr) {
        cudaStreamCreateWithFlags(&side, cudaStreamNonBlocking);
        cudaEventCreateWithFlags(&ev_fork, cudaEventDisableTiming);
        cudaEventCreateWithFlags(&ev_join, cudaEventDisableTiming);
    }

    // fork
    cudaEventRecord(ev_fork, 0);
    cudaStreamWaitEvent(side, ev_fork, 0);

    se_produce<<<NPLANE, 256>>>(x, w1, g1, b1, m1, v1, w2, g2, b2, m2, v2);
    se_consume<<<CONS, 256, 0, side>>>(x, y);

    // join
    cudaEventRecord(ev_join, side);
    cudaStreamWaitEvent(0, ev_join, 0);
}

// round 16
// speedup vs baseline: 1.9731x; 1.1051x over previous
#include <cuda_runtime.h>

#define BB 32
#define CC 512
#define HC 128
#define HW 4096
#define NPLANE (BB * CC)
#define EPS_BN 0.001f

// scratch (no device allocations allowed anywhere)
__device__ float g_s[BB * CC];      // pooled means [B, C]
__device__ float g_es[BB * CC];     // e * scale2   [B, C]
__device__ float g_shift[CC];       // shift2       [C]

// ---------------------------------------------------------------------------
// Kernel 1: per-plane mean, full grid (proven 41us @ 6.6TB/s). Default
// caching leaves the ~126MB tail of x resident in L2 for kernel 3.
// ---------------------------------------------------------------------------
__global__ void __launch_bounds__(256) se_reduce(const float* __restrict__ x) {
    const int plane = blockIdx.x;
    const float4* xp = reinterpret_cast<const float4*>(x + (size_t)plane * HW)
                       + threadIdx.x;
    float sum = 0.f;
#pragma unroll
    for (int i = 0; i < 4; i++) {
        float4 v = xp[i * 256];
        sum += (v.x + v.y) + (v.z + v.w);
    }
#pragma unroll
    for (int o = 16; o > 0; o >>= 1)
        sum += __shfl_down_sync(0xffffffffu, sum, o);

    __shared__ float red[8];
    if ((threadIdx.x & 31) == 0) red[threadIdx.x >> 5] = sum;
    __syncthreads();
    if (threadIdx.x == 0) {
        float s = 0.f;
#pragma unroll
        for (int i = 0; i < 8; i++) s += red[i];
        g_s[plane] = s * (1.0f / HW);
    }
    cudaTriggerProgrammaticLaunchCompletion();
}

// ---------------------------------------------------------------------------
// Kernel 2: excitation MLP, one block per batch; PDL-gated on the reduce.
// ---------------------------------------------------------------------------
__global__ void __launch_bounds__(256) se_excite(
    const float* __restrict__ w1, const float* __restrict__ g1,
    const float* __restrict__ b1, const float* __restrict__ m1,
    const float* __restrict__ v1, const float* __restrict__ w2,
    const float* __restrict__ g2, const float* __restrict__ b2,
    const float* __restrict__ m2, const float* __restrict__ v2) {
    __shared__ float s_s[CC];
    __shared__ float s_h[HC];
    const int b = blockIdx.x, wid = threadIdx.x >> 5, lane = threadIdx.x & 31;

    cudaGridDependencySynchronize();

    for (int i = threadIdx.x; i < CC; i += 256) s_s[i] = g_s[b * CC + i];
    __syncthreads();

#pragma unroll 2
    for (int r = 0; r < 16; r++) {
        const int j = wid * 16 + r;
        const float* wr = w1 + j * CC;
        float acc = 0.f;
#pragma unroll
        for (int i = 0; i < CC / 32; i++)
            acc = fmaf(wr[lane + 32 * i], s_s[lane + 32 * i], acc);
#pragma unroll
        for (int o = 16; o > 0; o >>= 1)
            acc += __shfl_down_sync(0xffffffffu, acc, o);
        if (lane == 0) {
            float hv = (acc - m1[j]) * (g1[j] * rsqrtf(v1[j] + EPS_BN)) + b1[j];
            s_h[j] = fmaxf(hv, 0.f);
        }
    }
    __syncthreads();

#pragma unroll 2
    for (int r = 0; r < 64; r++) {
        const int c = wid * 64 + r;
        const float* wr = w2 + c * HC;
        float acc = 0.f;
#pragma unroll
        for (int i = 0; i < HC / 32; i++)
            acc = fmaf(wr[lane + 32 * i], s_h[lane + 32 * i], acc);
#pragma unroll
        for (int o = 16; o > 0; o >>= 1)
            acc += __shfl_down_sync(0xffffffffu, acc, o);
        if (lane == 0) {
            const float sc2 = g2[c] * rsqrtf(v2[c] + EPS_BN);
            g_es[b * CC + c] = acc * sc2;
            if (b == 0) g_shift[c] = fmaf(-m2[c], sc2, b2[c]);
        }
    }
    __syncthreads();
    cudaTriggerProgrammaticLaunchCompletion();
}

// ---------------------------------------------------------------------------
// Kernel 3: PERSISTENT scale — 512 blocks, block bid walks batches k=31..0
// handling plane k*512+bid (reverse order: first reads hit the L2 tail).
// This shape measured 6.1 TB/s mixed R/W in R15 (vs 3.6 TB/s at 8192 CTAs).
// First plane is prefetched before the PDL dependency sync to overlap the
// excite kernel and the reduce drain.
// ---------------------------------------------------------------------------
__global__ void __launch_bounds__(256) se_scale(const float* __restrict__ x,
                                                float* __restrict__ y) {
    const int tid = threadIdx.x;

    // ---- prefetch plane for k=31 before waiting on excite ----
    int plane = (BB - 1) * CC + blockIdx.x;
    size_t base = (size_t)plane * (HW / 4);
    const float4* xp = reinterpret_cast<const float4*>(x) + base + tid;

    float4 v[4];
#pragma unroll
    for (int i = 0; i < 4; i++) v[i] = __ldcg(xp + i * 256);

    cudaGridDependencySynchronize();               // g_es / g_shift ready

    const float shift = g_shift[blockIdx.x & (CC - 1)];  // same c every iter

    for (int k = BB - 1; k >= 0; k--) {
        const float es = __ldcg(&g_es[plane]);
        float4* yp = reinterpret_cast<float4*>(y) + base + tid;

        // compute+store current plane
#pragma unroll
        for (int i = 0; i < 4; i++) {
            float4 o;
            o.x = fmaf(v[i].x, es, shift);
            o.y = fmaf(v[i].y, es, shift);
            o.z = fmaf(v[i].z, es, shift);
            o.w = fmaf(v[i].w, es, shift);
            __stcs(yp + i * 256, o);
        }

        // load next plane (k-1)
        if (k > 0) {
            plane -= CC;
            base = (size_t)plane * (HW / 4);
            xp = reinterpret_cast<const float4*>(x) + base + tid;
#pragma unroll
            for (int i = 0; i < 4; i++) v[i] = __ldcg(xp + i * 256);
        }
    }
}

// ---------------------------------------------------------------------------
extern "C" void kernel_launch(void* const* d_in, const int* in_sizes, int n_in,
                              void* d_out, int out_size) {
    const float* x  = (const float*)d_in[0];
    const float* w1 = (const float*)d_in[1];
    const float* g1 = (const float*)d_in[2];
    const float* b1 = (const float*)d_in[3];
    const float* m1 = (const float*)d_in[4];
    const float* v1 = (const float*)d_in[5];
    const float* w2 = (const float*)d_in[6];
    const float* g2 = (const float*)d_in[7];
    const float* b2 = (const float*)d_in[8];
    const float* m2 = (const float*)d_in[9];
    const float* v2 = (const float*)d_in[10];
    float* y = (float*)d_out;

    se_reduce<<<NPLANE, 256>>>(x);

    cudaLaunchAttribute attr[1];
    attr[0].id = cudaLaunchAttributeProgrammaticStreamSerialization;
    attr[0].val.programmaticStreamSerializationAllowed = 1;

    cudaLaunchConfig_t cfg2 = {};
    cfg2.gridDim = dim3(BB); cfg2.blockDim = dim3(256);
    cfg2.stream = 0; cfg2.attrs = attr; cfg2.numAttrs = 1;
    if (cudaLaunchKernelEx(&cfg2, se_excite,
                           w1, g1, b1, m1, v1, w2, g2, b2, m2, v2) != cudaSuccess) {
        (void)cudaGetLastError();
        se_excite<<<BB, 256>>>(w1, g1, b1, m1, v1, w2, g2, b2, m2, v2);
    }

    cudaLaunchConfig_t cfg3 = {};
    cfg3.gridDim = dim3(CC); cfg3.blockDim = dim3(256);
    cfg3.stream = 0; cfg3.attrs = attr; cfg3.numAttrs = 1;
    if (cudaLaunchKernelEx(&cfg3, se_scale, x, y) != cudaSuccess) {
        (void)cudaGetLastError();
        se_scale<<<CC, 256>>>(x, y);
    }
}